// round 2
// baseline (speedup 1.0000x reference)
#include <cuda_runtime.h>
#include <math.h>

// Problem constants (fixed shapes for this problem instance)
#define NN   1024     // notes
#define LL   32768    // max note length
#define WW   1024     // hann window length
#define HH   8        // harmonics
#define KK   128      // FIR taps
#define TILE 2048     // output samples per block
#define NTHREADS 256
#define OPT  8        // outputs per thread (TILE = NTHREADS*OPT)

// Scratch (device globals; no allocation allowed)
__device__ float g_amps[NN * HH];   // softplus(z) * vel, per note per harmonic
__device__ float g_hann[WW];
__device__ float g_fir_rev[KK];     // g[j] = fir[K-1-j]
__device__ int   g_olen[NN];

// ---------------------------------------------------------------------------
// Accurate sin of an fp32 argument, |x| < ~1e5.
// Cody-Waite 3-term reduction (all steps single-rounded via fmaf), then
// sin.approx on |r| <= pi (+eps). Total abs error ~2.5e-6 vs libm sinf(x).
// Deliberately flag-independent (no reliance on -use_fast_math behavior).
// ---------------------------------------------------------------------------
__device__ __forceinline__ float sin_ref(float x) {
    const float INV2PI = 0.15915494309189535f;
    float k = rintf(x * INV2PI);                      // k <= ~12520, exact fp32
    float r = fmaf(k, -6.28125f, x);                  // C1: 402*2^-6 (exact prods)
    r = fmaf(k, -1.9359588623046875e-3f, r);          // C2: 1015*2^-19
    r = fmaf(k,  6.5168271821061e-7f,  r);            // -C3 (2pi = C1+C2+C3)
    return __sinf(r);                                 // sin.approx, |r|<=pi
}

// Accurate-enough tanh, flag-independent (avoid tanh.approx ~2^-10 error).
__device__ __forceinline__ float tanh_ref(float x) {
    float ax = fabsf(x);
    float r;
    if (ax >= 9.0f) {
        r = 1.0f;
    } else {
        float e = __expf(2.0f * ax);                  // <= e^18 ~ 6.6e7
        r = 1.0f - __fdividef(2.0f, e + 1.0f);
    }
    return copysignf(r, x);
}

// ---------------------------------------------------------------------------
// Prep kernel: per-note MLPs (time latent -> amps), hann table, reversed FIR.
// 4 blocks x 256 threads; thread i handles note i (i < NN).
// ---------------------------------------------------------------------------
__global__ void prep_kernel(
    const float* __restrict__ freq, const float* __restrict__ velocity,
    const float* __restrict__ w1,  const float* __restrict__ b1,
    const float* __restrict__ w2,  const float* __restrict__ b2,
    const float* __restrict__ ws1, const float* __restrict__ bs1,
    const float* __restrict__ ws2, const float* __restrict__ bs2,
    const float* __restrict__ fir,
    const int*   __restrict__ starts, const int* __restrict__ lengths,
    int D)
{
    int i = blockIdx.x * blockDim.x + threadIdx.x;

    if (i < KK) g_fir_rev[i] = fir[KK - 1 - i];

    if (i < WW) {
        // exactly replicate reference arg: fl(fl(2pi_f32 * n) / 1024)
        float a = 6.283185307179586f * (float)i * (1.0f / 1024.0f);
        double c = cos((double)a);                    // tiny kernel: DP is fine
        g_hann[i] = 0.5f * (1.0f - (float)c);
    }

    if (i < NN) {
        int st = starts[i];
        int en = st + lengths[i];
        int ol = min(en, D) - st;
        ol = max(0, min(ol, LL));
        g_olen[i] = ol;

        // time embedder: Linear(1,32) -> ReLU -> Linear(32,2)
        float nt = (float)st / (float)D;
        float lat0 = b2[0], lat1 = b2[1];
        #pragma unroll 8
        for (int j = 0; j < 32; ++j) {
            float h = fmaxf(fmaf(nt, w1[j], b1[j]), 0.0f);
            lat0 = fmaf(h, w2[j * 2 + 0], lat0);
            lat1 = fmaf(h, w2[j * 2 + 1], lat1);
        }

        float vel = velocity[i] * (1.0f / 127.0f);
        float feat0 = freq[i], feat1 = vel;

        // synth MLP: (4 -> 64 -> 8), softplus on output
        float z[HH];
        #pragma unroll
        for (int h = 0; h < HH; ++h) z[h] = bs2[h];
        #pragma unroll 4
        for (int j = 0; j < 64; ++j) {
            float h2 = bs1[j];
            h2 = fmaf(feat0, ws1[0 * 64 + j], h2);
            h2 = fmaf(feat1, ws1[1 * 64 + j], h2);
            h2 = fmaf(lat0,  ws1[2 * 64 + j], h2);
            h2 = fmaf(lat1,  ws1[3 * 64 + j], h2);
            h2 = fmaxf(h2, 0.0f);
            #pragma unroll
            for (int h = 0; h < HH; ++h)
                z[h] = fmaf(h2, ws2[j * HH + h], z[h]);
        }
        #pragma unroll
        for (int h = 0; h < HH; ++h) {
            float zz = z[h];
            float sp = fmaxf(zz, 0.0f) + log1pf(__expf(-fabsf(zz)));
            g_amps[i * HH + h] = sp * vel;            // fold vel into amps
        }
    }
}

// ---------------------------------------------------------------------------
// Zero the output (harness poisons d_out).
// ---------------------------------------------------------------------------
__global__ void zero_kernel(float* __restrict__ out, int n) {
    int i = blockIdx.x * blockDim.x + threadIdx.x;
    if (i < n) out[i] = 0.0f;
}

// ---------------------------------------------------------------------------
// Main kernel: one block per (tile, note). Synthesize seg into smem
// (9/8-padded for conflict-free stride-8 access), 128-tap FIR with a sliding
// register window (8 consecutive outputs/thread), tanh, RED.ADD scatter.
// ---------------------------------------------------------------------------
#define IDX9(i) ((i) + ((i) >> 3))
#define SEG_EXT (TILE + 128)                 // [t0-127, t0+TILE] inclusive-ish

__global__ void __launch_bounds__(NTHREADS)
synth_kernel(const float* __restrict__ freq,
             const int*   __restrict__ starts,
             float*       __restrict__ out)
{
    const int note = blockIdx.y;
    const int olen = g_olen[note];
    const int t0   = blockIdx.x * TILE;
    if (t0 >= olen) return;                  // uniform early exit

    __shared__ float s_seg[SEG_EXT + (SEG_EXT >> 3)];  // 2448 floats
    __shared__ float s_fir[KK];

    const int tid = threadIdx.x;
    if (tid < KK) s_fir[tid] = g_fir_rev[tid];

    // per-note constants (uniform loads)
    const float f0 = __ldg(&freq[note]);
    const int   start = __ldg(&starts[note]);
    float amp[HH];
    #pragma unroll
    for (int h = 0; h < HH; ++h) amp[h] = __ldg(&g_amps[note * HH + h]);

    // ---- phase 1: synthesize windowed/masked segment into smem ----
    // s_seg[idx9(e)] = x(t0 - 127 + e),  e in [0, SEG_EXT)
    const int wstart = olen - WW;            // window begins here
    for (int e = tid; e < SEG_EXT; e += NTHREADS) {
        int t = t0 - 127 + e;
        float v = 0.0f;
        if (t >= 0 && t < olen) {
            float ph = f0 * (float)t;        // matches ref fp32 phase
            float acc = 0.0f;
            #pragma unroll
            for (int h = 1; h <= HH; ++h) {
                float arg = (float)h * ph;   // matches ref fl(h*phase)
                acc = fmaf(amp[h - 1], sin_ref(arg), acc);
            }
            int wpos = t - wstart;
            if (wpos >= 0) acc *= g_hann[wpos];   // wpos < WW guaranteed
            v = acc;
        }
        s_seg[IDX9(e)] = v;
    }
    __syncthreads();

    // ---- phase 2: causal FIR + tanh + scatter-add ----
    const int limit = olen - t0;             // valid outputs: r < limit
    const int r0 = tid * OPT;
    if (r0 < limit) {
        float acc[OPT];
        float w[OPT];
        #pragma unroll
        for (int m = 0; m < OPT; ++m) {
            acc[m] = 0.0f;
            int i = r0 + m;                  // = s index for j=127
            w[m] = s_seg[IDX9(i)];
        }
        // y(t0+r) = sum_j g[j] * s[r + 127 - j], j = 127..0 (k ascending)
        #pragma unroll 32
        for (int jj = 0; jj < KK; ++jj) {
            int j = KK - 1 - jj;
            float g = s_fir[j];              // broadcast
            #pragma unroll
            for (int m = 0; m < OPT; ++m) acc[m] = fmaf(g, w[m], acc[m]);
            #pragma unroll
            for (int m = 0; m < OPT - 1; ++m) w[m] = w[m + 1];
            int i = r0 + 8 + jj;             // stride-9 in smem: conflict-free
            w[OPT - 1] = s_seg[IDX9(i)];
        }
        float* __restrict__ gout = out + start + t0 + r0;
        #pragma unroll
        for (int m = 0; m < OPT; ++m) {
            if (r0 + m < limit)
                atomicAdd(gout + m, tanh_ref(acc[m]));   // compiles to RED.ADD
        }
    }
}

// ---------------------------------------------------------------------------
// Launch: zero -> prep -> synth (same stream, graph-capturable)
// ---------------------------------------------------------------------------
extern "C" void kernel_launch(void* const* d_in, const int* in_sizes, int n_in,
                              void* d_out, int out_size) {
    const float* freq     = (const float*)d_in[0];
    const float* velocity = (const float*)d_in[1];
    const float* w1       = (const float*)d_in[2];
    const float* b1       = (const float*)d_in[3];
    const float* w2       = (const float*)d_in[4];
    const float* b2       = (const float*)d_in[5];
    const float* ws1      = (const float*)d_in[6];
    const float* bs1      = (const float*)d_in[7];
    const float* ws2      = (const float*)d_in[8];
    const float* bs2      = (const float*)d_in[9];
    const float* fir      = (const float*)d_in[10];
    const int*   starts   = (const int*)d_in[11];
    const int*   lengths  = (const int*)d_in[12];
    float* out = (float*)d_out;
    const int D = out_size;                  // duration_samples == out_size

    zero_kernel<<<(D + 511) / 512, 512>>>(out, D);
    prep_kernel<<<4, 256>>>(freq, velocity, w1, b1, w2, b2,
                            ws1, bs1, ws2, bs2, fir, starts, lengths, D);
    dim3 grid(LL / TILE, NN);                // 16 x 1024 blocks, early-exit culls
    synth_kernel<<<grid, NTHREADS>>>(freq, starts, out);
}

// round 4
// speedup vs baseline: 1.0223x; 1.0223x over previous
#include <cuda_runtime.h>
#include <math.h>

// Problem constants (fixed shapes for this problem instance)
#define NN   1024     // notes
#define LL   32768    // max note length
#define WW   1024     // hann window length
#define HH   8        // harmonics
#define KK   128      // FIR taps
#define TILE 2048     // output samples per block
#define NTHREADS 256
#define OPT  8        // outputs per thread (TILE = NTHREADS*OPT)

// Scratch (device globals; no allocation allowed)
__device__ float g_amps[NN * HH];   // softplus(z) * vel, per note per harmonic
__device__ float g_hann[WW];
__device__ int   g_olen[NN];

// ---------------------------------------------------------------------------
// Packed f32x2 helpers (Blackwell FFMA2 — only reachable via PTX)
// ---------------------------------------------------------------------------
__device__ __forceinline__ unsigned long long pack2(float lo, float hi) {
    unsigned long long r;
    asm("mov.b64 %0, {%1, %2};" : "=l"(r) : "f"(lo), "f"(hi));
    return r;
}
__device__ __forceinline__ void unpack2(unsigned long long v, float& lo, float& hi) {
    asm("mov.b64 {%0, %1}, %2;" : "=f"(lo), "=f"(hi) : "l"(v));
}
__device__ __forceinline__ unsigned long long fma2(unsigned long long a,
                                                   unsigned long long b,
                                                   unsigned long long c) {
    unsigned long long d;
    asm("fma.rn.f32x2 %0, %1, %2, %3;" : "=l"(d) : "l"(a), "l"(b), "l"(c));
    return d;
}

// ---------------------------------------------------------------------------
// Accurate sin of an fp32 argument, |x| < ~1e5.
// Cody-Waite 3-term reduction (all steps single-rounded via fmaf), then
// sin.approx on |r| <= pi. Total abs error ~2.5e-6 vs libm sinf(x).
// ---------------------------------------------------------------------------
__device__ __forceinline__ float sin_ref(float x) {
    const float INV2PI = 0.15915494309189535f;
    float k = rintf(x * INV2PI);                      // k <= ~12520, exact fp32
    float r = fmaf(k, -6.28125f, x);                  // C1: exact products
    r = fmaf(k, -1.9359588623046875e-3f, r);          // C2
    r = fmaf(k,  6.5168271821061e-7f,  r);            // C3 (2pi = C1+C2+C3)
    return __sinf(r);                                 // sin.approx, |r|<=pi
}

// Accurate-enough tanh, flag-independent (avoid tanh.approx ~2^-10 error).
__device__ __forceinline__ float tanh_ref(float x) {
    float ax = fabsf(x);
    float r;
    if (ax >= 9.0f) {
        r = 1.0f;
    } else {
        float e = __expf(2.0f * ax);
        r = 1.0f - __fdividef(2.0f, e + 1.0f);
    }
    return copysignf(r, x);
}

// ---------------------------------------------------------------------------
// Prep kernel: per-note MLPs (time latent -> amps), hann table.
// ---------------------------------------------------------------------------
__global__ void prep_kernel(
    const float* __restrict__ freq, const float* __restrict__ velocity,
    const float* __restrict__ w1,  const float* __restrict__ b1,
    const float* __restrict__ w2,  const float* __restrict__ b2,
    const float* __restrict__ ws1, const float* __restrict__ bs1,
    const float* __restrict__ ws2, const float* __restrict__ bs2,
    const int*   __restrict__ starts, const int* __restrict__ lengths,
    int D)
{
    int i = blockIdx.x * blockDim.x + threadIdx.x;

    if (i < WW) {
        // exactly replicate reference arg: fl(fl(2pi_f32 * n) / 1024)
        float a = 6.283185307179586f * (float)i * (1.0f / 1024.0f);
        double c = cos((double)a);
        g_hann[i] = 0.5f * (1.0f - (float)c);
    }

    if (i < NN) {
        int st = starts[i];
        int en = st + lengths[i];
        int ol = min(en, D) - st;
        ol = max(0, min(ol, LL));
        g_olen[i] = ol;

        // time embedder: Linear(1,32) -> ReLU -> Linear(32,2)
        float nt = (float)st / (float)D;
        float lat0 = b2[0], lat1 = b2[1];
        #pragma unroll 8
        for (int j = 0; j < 32; ++j) {
            float h = fmaxf(fmaf(nt, w1[j], b1[j]), 0.0f);
            lat0 = fmaf(h, w2[j * 2 + 0], lat0);
            lat1 = fmaf(h, w2[j * 2 + 1], lat1);
        }

        float vel = velocity[i] * (1.0f / 127.0f);
        float feat0 = freq[i], feat1 = vel;

        // synth MLP: (4 -> 64 -> 8), softplus on output
        float z[HH];
        #pragma unroll
        for (int h = 0; h < HH; ++h) z[h] = bs2[h];
        #pragma unroll 4
        for (int j = 0; j < 64; ++j) {
            float h2 = bs1[j];
            h2 = fmaf(feat0, ws1[0 * 64 + j], h2);
            h2 = fmaf(feat1, ws1[1 * 64 + j], h2);
            h2 = fmaf(lat0,  ws1[2 * 64 + j], h2);
            h2 = fmaf(lat1,  ws1[3 * 64 + j], h2);
            h2 = fmaxf(h2, 0.0f);
            #pragma unroll
            for (int h = 0; h < HH; ++h)
                z[h] = fmaf(h2, ws2[j * HH + h], z[h]);
        }
        #pragma unroll
        for (int h = 0; h < HH; ++h) {
            float zz = z[h];
            float sp = fmaxf(zz, 0.0f) + log1pf(__expf(-fabsf(zz)));
            g_amps[i * HH + h] = sp * vel;            // fold vel into amps
        }
    }
}

// ---------------------------------------------------------------------------
// Zero the output (harness poisons d_out). Vectorized float4.
// ---------------------------------------------------------------------------
__global__ void zero_kernel(float4* __restrict__ out4, int n4, float* __restrict__ out, int n) {
    int i = blockIdx.x * blockDim.x + threadIdx.x;
    if (i < n4) out4[i] = make_float4(0.f, 0.f, 0.f, 0.f);
    int tail = n4 * 4 + i;
    if (tail < n && i < 4) out[tail] = 0.0f;
}

// ---------------------------------------------------------------------------
// Main kernel: one block per (tile, note). Synthesize seg into smem
// (9/8-padded for conflict-free stride-8 access), 128-tap FIR via packed
// FFMA2 with (m, m+4) output pairing, tanh, RED.ADD scatter.
//
// jax conv is CROSS-CORRELATION with left pad (K-1):
//   y(t) = sum_{k=0..127} fir[k] * x(t - 127 + k)
// With s[e] = x(t0 - 127 + e):  y[r] = sum_k fir[k] * s[r + k]  (UNREVERSED fir)
// ---------------------------------------------------------------------------
#define IDX9(i) ((i) + ((i) >> 3))
#define SEG_EXT (TILE + 128)                 // s indices [0, TILE+127]

__global__ void __launch_bounds__(NTHREADS)
synth_kernel(const float* __restrict__ freq,
             const int*   __restrict__ starts,
             const float* __restrict__ fir,
             float*       __restrict__ out)
{
    const int note = blockIdx.y;
    const int olen = g_olen[note];
    const int t0   = blockIdx.x * TILE;
    if (t0 >= olen) return;                  // uniform early exit

    __shared__ float s_seg[SEG_EXT + (SEG_EXT >> 3)];      // 2448 floats
    __shared__ unsigned long long s_fir2[KK];              // (fir[k], fir[k]) pairs

    const int tid = threadIdx.x;
    if (tid < KK) {
        float g = __ldg(&fir[tid]);          // UNREVERSED tap
        s_fir2[tid] = pack2(g, g);
    }

    // per-note constants (uniform loads)
    const float f0 = __ldg(&freq[note]);
    const int   start = __ldg(&starts[note]);
    float amp[HH];
    #pragma unroll
    for (int h = 0; h < HH; ++h) amp[h] = __ldg(&g_amps[note * HH + h]);

    // ---- phase 1: synthesize windowed/masked segment into smem ----
    // s_seg[idx9(e)] = x(t0 - 127 + e),  e in [0, SEG_EXT)
    const int wstart = olen - WW;            // window begins here
    for (int e = tid; e < SEG_EXT; e += NTHREADS) {
        int t = t0 - 127 + e;
        float v = 0.0f;
        if (t >= 0 && t < olen) {
            float ph = f0 * (float)t;        // matches ref fp32 phase
            float acc = 0.0f;
            #pragma unroll
            for (int h = 1; h <= HH; ++h) {
                float arg = (float)h * ph;   // matches ref fl(h*phase)
                acc = fmaf(amp[h - 1], sin_ref(arg), acc);
            }
            int wpos = t - wstart;
            if (wpos >= 0) acc *= g_hann[wpos];   // wpos < WW guaranteed
            v = acc;
        }
        s_seg[IDX9(e)] = v;
    }
    __syncthreads();

    // ---- phase 2: causal FIR (packed FFMA2) + tanh + scatter-add ----
    // y[r] = sum_{k=0..127} fir[k] * s[r + k]
    // Output pairing (r0+m, r0+m+4):  W[m] = (s[r0+m+k], s[r0+m+4+k]) at tap k.
    // Per tap: accp[m] += (fir,fir) * W[m]; shift; refill
    //          W[3] <- (hi(old W[0]) = s[r0+k+4], s[r0+k+8]).
    const int limit = olen - t0;             // valid outputs: r < limit
    const int r0 = tid * OPT;
    if (r0 < limit) {
        unsigned long long accp[4], W[4];
        #pragma unroll
        for (int m = 0; m < 4; ++m) {
            accp[m] = 0ull;
            W[m] = pack2(s_seg[IDX9(r0 + m)], s_seg[IDX9(r0 + m + 4)]);
        }
        #pragma unroll 32
        for (int k = 0; k < KK; ++k) {
            unsigned long long g2 = s_fir2[k];         // LDS.64 broadcast
            #pragma unroll
            for (int m = 0; m < 4; ++m) accp[m] = fma2(g2, W[m], accp[m]);
            float newhi = s_seg[IDX9(r0 + k + 8)];     // stride-9: conflict-free
            float lo, carry;
            unpack2(W[0], lo, carry);                  // carry = s[r0+k+4]
            W[0] = W[1];
            W[1] = W[2];
            W[2] = W[3];
            W[3] = pack2(carry, newhi);
        }
        // unpack: accp[m] = (y[r0+m], y[r0+m+4])
        float acc[OPT];
        #pragma unroll
        for (int m = 0; m < 4; ++m) unpack2(accp[m], acc[m], acc[m + 4]);

        float* __restrict__ gout = out + start + t0 + r0;
        #pragma unroll
        for (int m = 0; m < OPT; ++m) {
            if (r0 + m < limit)
                atomicAdd(gout + m, tanh_ref(acc[m]));   // compiles to RED.ADD
        }
    }
}

// ---------------------------------------------------------------------------
// Launch: zero -> prep -> synth (same stream, graph-capturable)
// ---------------------------------------------------------------------------
extern "C" void kernel_launch(void* const* d_in, const int* in_sizes, int n_in,
                              void* d_out, int out_size) {
    const float* freq     = (const float*)d_in[0];
    const float* velocity = (const float*)d_in[1];
    const float* w1       = (const float*)d_in[2];
    const float* b1       = (const float*)d_in[3];
    const float* w2       = (const float*)d_in[4];
    const float* b2       = (const float*)d_in[5];
    const float* ws1      = (const float*)d_in[6];
    const float* bs1      = (const float*)d_in[7];
    const float* ws2      = (const float*)d_in[8];
    const float* bs2      = (const float*)d_in[9];
    const float* fir      = (const float*)d_in[10];
    const int*   starts   = (const int*)d_in[11];
    const int*   lengths  = (const int*)d_in[12];
    float* out = (float*)d_out;
    const int D = out_size;                  // duration_samples == out_size

    int n4 = D / 4;
    zero_kernel<<<(n4 + 511) / 512, 512>>>((float4*)out, n4, out, D);
    prep_kernel<<<4, 256>>>(freq, velocity, w1, b1, w2, b2,
                            ws1, bs1, ws2, bs2, starts, lengths, D);
    dim3 grid(LL / TILE, NN);                // 16 x 1024 blocks, early-exit culls
    synth_kernel<<<grid, NTHREADS>>>(freq, starts, fir, out);
}